// round 7
// baseline (speedup 1.0000x reference)
#include <cuda_runtime.h>
#include <math.h>

#define HW 65536
#define BRS (4 * 16 * HW)   // per-branch output stride (4,194,304 floats)

// ---------------- device scratch (no allocation allowed) -------------------
__device__ float g_x   [4 * 16 * HW];   // in_conv output     [b][c][h][w]
__device__ float g_c   [4 * 16 * HW];   // per-branch conv    [b][c][h][w]
__device__ float g_br  [4 * BRS];       // branch outputs     [br][b][c][w][h] (transposed)
__device__ float g_outs[4 * 16 * HW];   // max+mean combined  [b][c][w][h]
__device__ float g_mask[4 * HW];        // sigmoid mask       [b][w][h]
__device__ float g_k3  [256 * 8];       // softmax(scales2)
__device__ float g_k4  [256];           // softmax(scales3)  [g][e]
__device__ float g_s1  [4];             // softmax(scales1)

// ---------------------------------------------------------------------------
__global__ void prep_kernel(const float* __restrict__ s1,
                            const float* __restrict__ s2,
                            const float* __restrict__ s3) {
    int t = threadIdx.x;  // 256 threads
    {
        const float* row = s2 + t * 8;
        float m = row[0];
        #pragma unroll
        for (int j = 1; j < 8; ++j) m = fmaxf(m, row[j]);
        float e[8], sum = 0.f;
        #pragma unroll
        for (int j = 0; j < 8; ++j) { e[j] = expf(row[j] - m); sum += e[j]; }
        float iv = 1.f / sum;
        #pragma unroll
        for (int j = 0; j < 8; ++j) g_k3[t * 8 + j] = e[j] * iv;
    }
    if (t < 16) {
        const float* row = s3 + t * 16;
        float m = row[0];
        #pragma unroll
        for (int j = 1; j < 16; ++j) m = fmaxf(m, row[j]);
        float e[16], sum = 0.f;
        #pragma unroll
        for (int j = 0; j < 16; ++j) { e[j] = expf(row[j] - m); sum += e[j]; }
        float iv = 1.f / sum;
        #pragma unroll
        for (int j = 0; j < 16; ++j) g_k4[t * 16 + j] = e[j] * iv;
    }
    if (t == 0) {
        float m = fmaxf(fmaxf(s1[0], s1[1]), fmaxf(s1[2], s1[3]));
        float e0 = expf(s1[0] - m), e1 = expf(s1[1] - m);
        float e2 = expf(s1[2] - m), e3 = expf(s1[3] - m);
        float iv = 1.f / (e0 + e1 + e2 + e3);
        g_s1[0] = e0 * iv; g_s1[1] = e1 * iv; g_s1[2] = e2 * iv; g_s1[3] = e3 * iv;
    }
}

// ---------------------------------------------------------------------------
// 1x1 conv 64 -> 16 (+bias): one thread per pixel, 16 outputs.
__global__ void in_conv(const float* __restrict__ cen,
                        const float* __restrict__ w,
                        const float* __restrict__ bias) {
    __shared__ float sw[1024];
    __shared__ float sb[16];
    int tid = threadIdx.x;
    for (int i = tid; i < 1024; i += 256) sw[i] = w[i];
    if (tid < 16) sb[tid] = bias[tid];
    __syncthreads();
    int idx = blockIdx.x * 256 + tid;          // 0 .. 262143
    int b = idx >> 16, p = idx & 65535;
    float acc[16];
    #pragma unroll
    for (int c = 0; c < 16; ++c) acc[c] = sb[c];
    const float* cp = cen + (size_t)b * 64 * HW + p;
    #pragma unroll 4
    for (int ci = 0; ci < 64; ++ci) {
        float v = cp[(size_t)ci * HW];
        #pragma unroll
        for (int c = 0; c < 16; ++c) acc[c] = fmaf(sw[c * 64 + ci], v, acc[c]);
    }
    float* xp = g_x + (size_t)b * 16 * HW + p;
    #pragma unroll
    for (int c = 0; c < 16; ++c) xp[(size_t)c * HW] = acc[c];
}

// ---------------------------------------------------------------------------
// KxK conv 16 -> 16 (+bias), SAME padding. Tile 32w x 16h, 256 threads (32,8).
template <int K>
__global__ void mid_conv(const float* __restrict__ w, const float* __restrict__ bias) {
    constexpr int P  = (K - 1) / 2;
    constexpr int TW = 32 + 2 * P;
    constexpr int TH = 16 + 2 * P;
    __shared__ float tile[TH][TW + 1];
    __shared__ float ws[16 * K * K];
    int b  = blockIdx.z;
    int h0 = blockIdx.y * 16, w0 = blockIdx.x * 32;
    int tx = threadIdx.x, ty = threadIdx.y;
    int tid = ty * 32 + tx;
    float acc[16][2];
    #pragma unroll
    for (int co = 0; co < 16; ++co) {
        float bv = __ldg(bias + co);
        acc[co][0] = bv; acc[co][1] = bv;
    }
    for (int ci = 0; ci < 16; ++ci) {
        __syncthreads();
        for (int i = tid; i < 16 * K * K; i += 256) {
            int co = i / (K * K), rc = i % (K * K);
            ws[i] = w[(co * 16 + ci) * K * K + rc];
        }
        const float* xp = g_x + (size_t)(b * 16 + ci) * HW;
        for (int i = tid; i < TH * TW; i += 256) {
            int th = i / TW, tw = i - th * TW;
            int hh = h0 + th - P, wv = w0 + tw - P;
            tile[th][tw] = ((unsigned)hh < 256u && (unsigned)wv < 256u)
                               ? xp[hh * 256 + wv] : 0.f;
        }
        __syncthreads();
        #pragma unroll
        for (int r = 0; r < K; ++r)
            #pragma unroll
            for (int c = 0; c < K; ++c) {
                float v0 = tile[ty + r][tx + c];
                float v1 = tile[ty + 8 + r][tx + c];
                #pragma unroll
                for (int co = 0; co < 16; ++co) {
                    float wv = ws[co * K * K + r * K + c];
                    acc[co][0] = fmaf(wv, v0, acc[co][0]);
                    acc[co][1] = fmaf(wv, v1, acc[co][1]);
                }
            }
    }
    #pragma unroll
    for (int co = 0; co < 16; ++co) {
        float* op = g_c + (size_t)(b * 16 + co) * HW + (h0 + ty) * 256 + w0 + tx;
        op[0]        = acc[co][0];
        op[8 * 256]  = acc[co][1];
    }
}

// ---------------------------------------------------------------------------
// Sign-flip bitonic sort of 256 values across a warp, 8 regs/lane,
// layout i = lane*8 + r, ascending.
__device__ __forceinline__ void cmpA(float& a, float& b) {
    float mn = fminf(a, b), mx = fmaxf(a, b); a = mn; b = mx;
}
__device__ __forceinline__ void cmpD(float& a, float& b) {
    float mn = fminf(a, b), mx = fmaxf(a, b); a = mx; b = mn;
}
__device__ __forceinline__ void inreg3(float s[8]) {
    cmpA(s[0], s[4]); cmpA(s[1], s[5]); cmpA(s[2], s[6]); cmpA(s[3], s[7]);
    cmpA(s[0], s[2]); cmpA(s[1], s[3]); cmpA(s[4], s[6]); cmpA(s[5], s[7]);
    cmpA(s[0], s[1]); cmpA(s[2], s[3]); cmpA(s[4], s[5]); cmpA(s[6], s[7]);
}
__device__ __forceinline__ void negif(float s[8], int f) {
    float sg = f ? -1.f : 1.f;
    #pragma unroll
    for (int r = 0; r < 8; ++r) s[r] *= sg;
}
template <int M>
__device__ __forceinline__ void shufstage(float s[8], bool keepmin) {
    #pragma unroll
    for (int r = 0; r < 8; ++r) {
        float o = __shfl_xor_sync(0xffffffffu, s[r], M);
        s[r] = keepmin ? fminf(s[r], o) : fmaxf(s[r], o);
    }
}
__device__ __forceinline__ void sort256(float s[8], int lane) {
    // phases k=1,2 : fully in-register, compile-time directions
    cmpA(s[0], s[1]); cmpD(s[2], s[3]); cmpA(s[4], s[5]); cmpD(s[6], s[7]);
    cmpA(s[0], s[2]); cmpA(s[1], s[3]); cmpD(s[4], s[6]); cmpD(s[5], s[7]);
    cmpA(s[0], s[1]); cmpA(s[2], s[3]); cmpD(s[4], s[5]); cmpD(s[6], s[7]);
    int b0 = lane & 1, b1 = (lane >> 1) & 1, b2 = (lane >> 2) & 1;
    int b3 = (lane >> 3) & 1, b4 = (lane >> 4) & 1;
    bool k1 = (lane & 1) == 0, k2 = (lane & 2) == 0, k4 = (lane & 4) == 0;
    bool k8 = (lane & 8) == 0, k16 = (lane & 16) == 0;
    // phase 3 (flip = b0)
    negif(s, b0);
    inreg3(s);
    // phase 4 (flip = b1)
    negif(s, b0 ^ b1);
    shufstage<1>(s, k1);
    inreg3(s);
    // phase 5 (flip = b2)
    negif(s, b1 ^ b2);
    shufstage<2>(s, k2);
    shufstage<1>(s, k1);
    inreg3(s);
    // phase 6 (flip = b3)
    negif(s, b2 ^ b3);
    shufstage<4>(s, k4);
    shufstage<2>(s, k2);
    shufstage<1>(s, k1);
    inreg3(s);
    // phase 7 (flip = b4)
    negif(s, b3 ^ b4);
    shufstage<8>(s, k8);
    shufstage<4>(s, k4);
    shufstage<2>(s, k2);
    shufstage<1>(s, k1);
    inreg3(s);
    // phase 8 (flip = 0)
    negif(s, b4);
    shufstage<16>(s, k16);
    shufstage<8>(s, k8);
    shufstage<4>(s, k4);
    shufstage<2>(s, k2);
    shufstage<1>(s, k1);
    inreg3(s);
}

// ---------------------------------------------------------------------------
// Fused: dilated directional diffs -> 16 expansion products -> sort along H
//        -> SiLU -> k4 reduce. Output transposed [b][c][w][h].
// 8 output columns per block (1 per warp). Column buffer stride CP=289 (odd)
// and per-column padding addr(h) = h + (h>>3): both the w-major fill and the
// stride-8 sort-layout reads are bank-conflict-free.
template <int S>
__global__ void __launch_bounds__(256) fused_branch(int br) {
    constexpr int NC = 8 + 2 * S;           // columns in tile
    constexpr int CP = 289;
    __shared__ float cs[NC * CP];
    __shared__ float k3s[128], k3r[128];    // [e][d] and rotated
    __shared__ float k4s[16];

    int b = blockIdx.z, g = blockIdx.y, w0 = blockIdx.x * 8;
    int tid  = threadIdx.x;
    int lane = tid & 31, warp = tid >> 5;

    if (tid < 128) {
        int e = tid >> 3, d = tid & 7;
        int row = g * 16 + e;
        k3s[tid] = g_k3[row * 8 + d];
        k3r[tid] = g_k3[row * 8 + ((d + 4) & 7)];
    }
    if (tid < 16) k4s[tid] = g_k4[g * 16 + tid];

    const float* cbase = g_c + (size_t)(b * 16 + g) * HW;
    // w-major fill: consecutive threads hit consecutive gmem addresses
    #pragma unroll 1
    for (int j = tid; j < NC * 256; j += 256) {
        int h   = j / NC;
        int col = j - h * NC;
        int wg  = w0 - S + col;
        float v = 0.f;
        if ((unsigned)wg < 256u) v = cbase[h * 256 + wg];
        cs[col * CP + h + (h >> 3)] = v;
    }
    __syncthreads();

    {
        int colc = warp + S;                // this warp's output column in tile
        const float* pC = cs + colc * CP;
        const float* pL = cs + (colc - S) * CP;
        const float* pR = cs + (colc + S) * CP;

        float cc[8], nb[8][8];
        #pragma unroll
        for (int r = 0; r < 8; ++r) {
            int h  = lane * 8 + r;           // sort-layout element index
            int hm = h - S, hp = h + S;
            bool vm = hm >= 0;
            bool vp = hp < 256;
            int  ai  = h  + (h  >> 3);
            int  aim = hm + (hm >> 3);
            int  aip = hp + (hp >> 3);
            cc[r]    = pC[ai];
            nb[0][r] = vm ? pL[aim] : 0.f;
            nb[1][r] = vm ? pC[aim] : 0.f;
            nb[2][r] = vm ? pR[aim] : 0.f;
            nb[3][r] = pL[ai];
            nb[4][r] = vp ? pR[aip] : 0.f;
            nb[5][r] = vp ? pC[aip] : 0.f;
            nb[6][r] = vp ? pL[aip] : 0.f;
            nb[7][r] = pR[ai];
        }

        float acc[8];
        #pragma unroll
        for (int r = 0; r < 8; ++r) acc[r] = 0.f;

        #pragma unroll 1
        for (int e = 0; e < 16; ++e) {
            float w1[8], w2[8];
            #pragma unroll
            for (int d = 0; d < 8; ++d) { w1[d] = k3s[e * 8 + d]; w2[d] = k3r[e * 8 + d]; }
            float s[8];
            #pragma unroll
            for (int r = 0; r < 8; ++r) {
                float A = nb[0][r] * w1[0];
                float B = nb[0][r] * w2[0];
                #pragma unroll
                for (int d = 1; d < 8; ++d) {
                    A = fmaf(nb[d][r], w1[d], A);
                    B = fmaf(nb[d][r], w2[d], B);
                }
                s[r] = (cc[r] - A) * (cc[r] - B);
            }
            sort256(s, lane);
            float k4e = k4s[e];
            #pragma unroll
            for (int r = 0; r < 8; ++r) {
                float v  = s[r];
                float sg = 1.f / (1.f + __expf(-v));
                acc[r] = fmaf(k4e * v, sg, acc[r]);
            }
        }

        int w = w0 + warp;
        float* op = g_br + (size_t)br * BRS + ((size_t)((b * 16 + g) * 256 + w)) * 256;
        float4 v0 = make_float4(acc[0], acc[1], acc[2], acc[3]);
        float4 v1 = make_float4(acc[4], acc[5], acc[6], acc[7]);
        reinterpret_cast<float4*>(op + lane * 8)[0] = v0;
        reinterpret_cast<float4*>(op + lane * 8)[1] = v1;
    }
}

// ---------------------------------------------------------------------------
__global__ void combine_kernel() {
    int idx = blockIdx.x * 256 + threadIdx.x;   // float4 index
    const float4* p0 = (const float4*)g_br;
    float4 v0 = p0[idx];
    float4 v1 = p0[BRS / 4 + idx];
    float4 v2 = p0[2 * (BRS / 4) + idx];
    float4 v3 = p0[3 * (BRS / 4) + idx];
    float4 o;
    o.x = fmaxf(fmaxf(v0.x, v1.x), fmaxf(v2.x, v3.x)) + 0.25f * (v0.x + v1.x + v2.x + v3.x);
    o.y = fmaxf(fmaxf(v0.y, v1.y), fmaxf(v2.y, v3.y)) + 0.25f * (v0.y + v1.y + v2.y + v3.y);
    o.z = fmaxf(fmaxf(v0.z, v1.z), fmaxf(v2.z, v3.z)) + 0.25f * (v0.z + v1.z + v2.z + v3.z);
    o.w = fmaxf(fmaxf(v0.w, v1.w), fmaxf(v2.w, v3.w)) + 0.25f * (v0.w + v1.w + v2.w + v3.w);
    ((float4*)g_outs)[idx] = o;
}

// ---------------------------------------------------------------------------
// 3x3 conv (no bias) on transposed layout + BN(eval) + SiLU + 1x1 -> sigmoid.
__global__ void post_conv(const float* __restrict__ wb,
                          const float* __restrict__ gamma,
                          const float* __restrict__ beta,
                          const float* __restrict__ mean,
                          const float* __restrict__ var,
                          const float* __restrict__ wout,
                          const float* __restrict__ bout) {
    __shared__ float tile[18][35];
    __shared__ float ws[16 * 9];
    int b  = blockIdx.z;
    int o0 = blockIdx.y * 16, i0 = blockIdx.x * 32;
    int tx = threadIdx.x, ty = threadIdx.y;
    int tid = ty * 32 + tx;
    float acc[16][2];
    #pragma unroll
    for (int co = 0; co < 16; ++co) { acc[co][0] = 0.f; acc[co][1] = 0.f; }
    for (int ci = 0; ci < 16; ++ci) {
        __syncthreads();
        for (int i = tid; i < 144; i += 256) {
            int co = i / 9, rc = i % 9;
            int bi = rc / 3, ao = rc % 3;
            ws[co * 9 + ao * 3 + bi] = wb[(co * 16 + ci) * 9 + bi * 3 + ao];
        }
        const float* xp = g_outs + (size_t)(b * 16 + ci) * HW;
        for (int i = tid; i < 18 * 34; i += 256) {
            int to = i / 34, ti = i - to * 34;
            int oo = o0 + to - 1, ii = i0 + ti - 1;
            tile[to][ti] = ((unsigned)oo < 256u && (unsigned)ii < 256u)
                               ? xp[oo * 256 + ii] : 0.f;
        }
        __syncthreads();
        #pragma unroll
        for (int a = 0; a < 3; ++a)
            #pragma unroll
            for (int bb = 0; bb < 3; ++bb) {
                float v0 = tile[ty + a][tx + bb];
                float v1 = tile[ty + 8 + a][tx + bb];
                #pragma unroll
                for (int co = 0; co < 16; ++co) {
                    float wv = ws[co * 9 + a * 3 + bb];
                    acc[co][0] = fmaf(wv, v0, acc[co][0]);
                    acc[co][1] = fmaf(wv, v1, acc[co][1]);
                }
            }
    }
    float m0 = 0.f, m1 = 0.f;
    #pragma unroll
    for (int co = 0; co < 16; ++co) {
        float sc = __ldg(gamma + co) * rsqrtf(__ldg(var + co) + 1e-5f);
        float sh = __ldg(beta + co) - __ldg(mean + co) * sc;
        float h0 = acc[co][0] * sc + sh;
        float h1 = acc[co][1] * sc + sh;
        h0 = h0 / (1.f + __expf(-h0));
        h1 = h1 / (1.f + __expf(-h1));
        float wv = __ldg(wout + co);
        m0 = fmaf(wv, h0, m0);
        m1 = fmaf(wv, h1, m1);
    }
    float bo = __ldg(bout);
    m0 = 1.f / (1.f + __expf(-(m0 + bo)));
    m1 = 1.f / (1.f + __expf(-(m1 + bo)));
    float* mp = g_mask + (size_t)b * HW + (o0 + ty) * 256 + i0 + tx;
    mp[0]       = m0;
    mp[8 * 256] = m1;
}

// ---------------------------------------------------------------------------
// Final: out = cen * (mask*m*s0 + m*s1 + s2*mask + s3), mask stored [b][w][h].
__global__ void final_kernel(const float* __restrict__ cen,
                             const float* __restrict__ mas,
                             float* __restrict__ out) {
    __shared__ float mt[32][33];
    int b  = blockIdx.z;
    int h0 = blockIdx.x * 32, w0 = blockIdx.y * 32;
    int tx = threadIdx.x, ty = threadIdx.y;
    #pragma unroll
    for (int k = 0; k < 4; ++k) {
        int wi = ty * 4 + k;
        mt[wi][tx] = g_mask[(size_t)b * HW + (w0 + wi) * 256 + h0 + tx];
    }
    __syncthreads();
    float s0 = g_s1[0], s1 = g_s1[1], s2 = g_s1[2], s3 = g_s1[3];
    int w = w0 + tx;
    #pragma unroll
    for (int k = 0; k < 4; ++k) {
        int h = h0 + ty * 4 + k;
        float mv = mt[tx][ty * 4 + k];
        float ms = mas[(size_t)b * HW + h * 256 + w];
        float m  = 1.f / (1.f + __expf(-ms));
        float coef = m * fmaf(mv, s0, s1) + fmaf(s2, mv, s3);
        size_t base = (size_t)b * 64 * HW + (size_t)h * 256 + w;
        #pragma unroll 4
        for (int c = 0; c < 64; ++c) {
            size_t o = base + (size_t)c * HW;
            out[o] = cen[o] * coef;
        }
    }
}

// ---------------------------------------------------------------------------
extern "C" void kernel_launch(void* const* d_in, const int* in_sizes, int n_in,
                              void* d_out, int out_size) {
    const float* cen      = (const float*)d_in[0];
    const float* mas      = (const float*)d_in[1];
    const float* w_in     = (const float*)d_in[2];
    const float* b_in     = (const float*)d_in[3];
    const float* w_c0     = (const float*)d_in[4];
    const float* b_c0     = (const float*)d_in[5];
    const float* w_c1     = (const float*)d_in[6];
    const float* b_c1     = (const float*)d_in[7];
    const float* w_c2     = (const float*)d_in[8];
    const float* b_c2     = (const float*)d_in[9];
    const float* w_c3     = (const float*)d_in[10];
    const float* b_c3     = (const float*)d_in[11];
    const float* scales1  = (const float*)d_in[12];
    const float* scales2  = (const float*)d_in[13];
    const float* scales3  = (const float*)d_in[14];
    const float* w_base   = (const float*)d_in[15];
    const float* bn_gamma = (const float*)d_in[16];
    const float* bn_beta  = (const float*)d_in[17];
    const float* bn_mean  = (const float*)d_in[18];
    const float* bn_var   = (const float*)d_in[19];
    const float* w_out    = (const float*)d_in[20];
    const float* b_out    = (const float*)d_in[21];
    float* out = (float*)d_out;

    prep_kernel<<<1, 256>>>(scales1, scales2, scales3);
    in_conv<<<1024, 256>>>(cen, w_in, b_in);

    dim3 cgrid(8, 16, 4), cblk(32, 8);
    dim3 fgrid(32, 16, 4);

    mid_conv<1><<<cgrid, cblk>>>(w_c0, b_c0);
    fused_branch<1><<<fgrid, 256>>>(0);

    mid_conv<3><<<cgrid, cblk>>>(w_c1, b_c1);
    fused_branch<3><<<fgrid, 256>>>(1);

    mid_conv<5><<<cgrid, cblk>>>(w_c2, b_c2);
    fused_branch<5><<<fgrid, 256>>>(2);

    mid_conv<7><<<cgrid, cblk>>>(w_c3, b_c3);
    fused_branch<7><<<fgrid, 256>>>(3);

    combine_kernel<<<BRS / 1024, 256>>>();

    post_conv<<<cgrid, cblk>>>(w_base, bn_gamma, bn_beta, bn_mean, bn_var,
                               w_out, b_out);

    final_kernel<<<dim3(8, 8, 4), dim3(32, 8)>>>(cen, mas, out);
}

// round 8
// speedup vs baseline: 1.0399x; 1.0399x over previous
#include <cuda_runtime.h>
#include <math.h>

#define HW 65536
#define BRS (4 * 16 * HW)   // per-branch output stride (4,194,304 floats)

// ---------------- device scratch (no allocation allowed) -------------------
__device__ float g_x   [4 * 16 * HW];   // in_conv output     [b][c][h][w]
__device__ float g_c   [4 * 16 * HW];   // per-branch conv    [b][c][h][w]
__device__ float g_br  [4 * BRS];       // branch outputs     [br][b][c][w][h] (transposed)
__device__ float g_outs[4 * 16 * HW];   // max+mean combined  [b][c][w][h]
__device__ float g_mask[4 * HW];        // sigmoid mask       [b][w][h]
__device__ float g_k3  [256 * 8];       // softmax(scales2)
__device__ float g_k4  [256];           // softmax(scales3)  [g][e]
__device__ float g_s1  [4];             // softmax(scales1)

// ---------------------------------------------------------------------------
__global__ void prep_kernel(const float* __restrict__ s1,
                            const float* __restrict__ s2,
                            const float* __restrict__ s3) {
    int t = threadIdx.x;  // 256 threads
    {
        const float* row = s2 + t * 8;
        float m = row[0];
        #pragma unroll
        for (int j = 1; j < 8; ++j) m = fmaxf(m, row[j]);
        float e[8], sum = 0.f;
        #pragma unroll
        for (int j = 0; j < 8; ++j) { e[j] = expf(row[j] - m); sum += e[j]; }
        float iv = 1.f / sum;
        #pragma unroll
        for (int j = 0; j < 8; ++j) g_k3[t * 8 + j] = e[j] * iv;
    }
    if (t < 16) {
        const float* row = s3 + t * 16;
        float m = row[0];
        #pragma unroll
        for (int j = 1; j < 16; ++j) m = fmaxf(m, row[j]);
        float e[16], sum = 0.f;
        #pragma unroll
        for (int j = 0; j < 16; ++j) { e[j] = expf(row[j] - m); sum += e[j]; }
        float iv = 1.f / sum;
        #pragma unroll
        for (int j = 0; j < 16; ++j) g_k4[t * 16 + j] = e[j] * iv;
    }
    if (t == 0) {
        float m = fmaxf(fmaxf(s1[0], s1[1]), fmaxf(s1[2], s1[3]));
        float e0 = expf(s1[0] - m), e1 = expf(s1[1] - m);
        float e2 = expf(s1[2] - m), e3 = expf(s1[3] - m);
        float iv = 1.f / (e0 + e1 + e2 + e3);
        g_s1[0] = e0 * iv; g_s1[1] = e1 * iv; g_s1[2] = e2 * iv; g_s1[3] = e3 * iv;
    }
}

// ---------------------------------------------------------------------------
// 1x1 conv 64 -> 16 (+bias): one thread per pixel, 16 outputs.
__global__ void in_conv(const float* __restrict__ cen,
                        const float* __restrict__ w,
                        const float* __restrict__ bias) {
    __shared__ float sw[1024];
    __shared__ float sb[16];
    int tid = threadIdx.x;
    for (int i = tid; i < 1024; i += 256) sw[i] = w[i];
    if (tid < 16) sb[tid] = bias[tid];
    __syncthreads();
    int idx = blockIdx.x * 256 + tid;          // 0 .. 262143
    int b = idx >> 16, p = idx & 65535;
    float acc[16];
    #pragma unroll
    for (int c = 0; c < 16; ++c) acc[c] = sb[c];
    const float* cp = cen + (size_t)b * 64 * HW + p;
    #pragma unroll 4
    for (int ci = 0; ci < 64; ++ci) {
        float v = cp[(size_t)ci * HW];
        #pragma unroll
        for (int c = 0; c < 16; ++c) acc[c] = fmaf(sw[c * 64 + ci], v, acc[c]);
    }
    float* xp = g_x + (size_t)b * 16 * HW + p;
    #pragma unroll
    for (int c = 0; c < 16; ++c) xp[(size_t)c * HW] = acc[c];
}

// ---------------------------------------------------------------------------
// KxK conv 16 -> 16 (+bias), SAME padding. Tile 32w x 16h, 256 threads (32,8).
template <int K>
__global__ void mid_conv(const float* __restrict__ w, const float* __restrict__ bias) {
    constexpr int P  = (K - 1) / 2;
    constexpr int TW = 32 + 2 * P;
    constexpr int TH = 16 + 2 * P;
    __shared__ float tile[TH][TW + 1];
    __shared__ float ws[16 * K * K];
    int b  = blockIdx.z;
    int h0 = blockIdx.y * 16, w0 = blockIdx.x * 32;
    int tx = threadIdx.x, ty = threadIdx.y;
    int tid = ty * 32 + tx;
    float acc[16][2];
    #pragma unroll
    for (int co = 0; co < 16; ++co) {
        float bv = __ldg(bias + co);
        acc[co][0] = bv; acc[co][1] = bv;
    }
    for (int ci = 0; ci < 16; ++ci) {
        __syncthreads();
        for (int i = tid; i < 16 * K * K; i += 256) {
            int co = i / (K * K), rc = i % (K * K);
            ws[i] = w[(co * 16 + ci) * K * K + rc];
        }
        const float* xp = g_x + (size_t)(b * 16 + ci) * HW;
        for (int i = tid; i < TH * TW; i += 256) {
            int th = i / TW, tw = i - th * TW;
            int hh = h0 + th - P, wv = w0 + tw - P;
            tile[th][tw] = ((unsigned)hh < 256u && (unsigned)wv < 256u)
                               ? xp[hh * 256 + wv] : 0.f;
        }
        __syncthreads();
        #pragma unroll
        for (int r = 0; r < K; ++r)
            #pragma unroll
            for (int c = 0; c < K; ++c) {
                float v0 = tile[ty + r][tx + c];
                float v1 = tile[ty + 8 + r][tx + c];
                #pragma unroll
                for (int co = 0; co < 16; ++co) {
                    float wv = ws[co * K * K + r * K + c];
                    acc[co][0] = fmaf(wv, v0, acc[co][0]);
                    acc[co][1] = fmaf(wv, v1, acc[co][1]);
                }
            }
    }
    #pragma unroll
    for (int co = 0; co < 16; ++co) {
        float* op = g_c + (size_t)(b * 16 + co) * HW + (h0 + ty) * 256 + w0 + tx;
        op[0]        = acc[co][0];
        op[8 * 256]  = acc[co][1];
    }
}

// ---------------------------------------------------------------------------
// Dual sign-flip bitonic sort: two independent 256-value warp sorts,
// stage-interleaved for ILP. Layout i = lane*8 + r, ascending.
__device__ __forceinline__ void cmpA(float& a, float& b) {
    float mn = fminf(a, b), mx = fmaxf(a, b); a = mn; b = mx;
}
__device__ __forceinline__ void cmpD(float& a, float& b) {
    float mn = fminf(a, b), mx = fmaxf(a, b); a = mx; b = mn;
}
__device__ __forceinline__ void inreg3x2(float s[8], float t[8]) {
    cmpA(s[0], s[4]); cmpA(t[0], t[4]); cmpA(s[1], s[5]); cmpA(t[1], t[5]);
    cmpA(s[2], s[6]); cmpA(t[2], t[6]); cmpA(s[3], s[7]); cmpA(t[3], t[7]);
    cmpA(s[0], s[2]); cmpA(t[0], t[2]); cmpA(s[1], s[3]); cmpA(t[1], t[3]);
    cmpA(s[4], s[6]); cmpA(t[4], t[6]); cmpA(s[5], s[7]); cmpA(t[5], t[7]);
    cmpA(s[0], s[1]); cmpA(t[0], t[1]); cmpA(s[2], s[3]); cmpA(t[2], t[3]);
    cmpA(s[4], s[5]); cmpA(t[4], t[5]); cmpA(s[6], s[7]); cmpA(t[6], t[7]);
}
__device__ __forceinline__ void negif2(float s[8], float t[8], int f) {
    float sg = f ? -1.f : 1.f;
    #pragma unroll
    for (int r = 0; r < 8; ++r) { s[r] *= sg; t[r] *= sg; }
}
template <int M>
__device__ __forceinline__ void shufstage2(float s[8], float t[8], bool keepmin) {
    #pragma unroll
    for (int r = 0; r < 8; ++r) {
        float o1 = __shfl_xor_sync(0xffffffffu, s[r], M);
        float o2 = __shfl_xor_sync(0xffffffffu, t[r], M);
        s[r] = keepmin ? fminf(s[r], o1) : fmaxf(s[r], o1);
        t[r] = keepmin ? fminf(t[r], o2) : fmaxf(t[r], o2);
    }
}
__device__ __forceinline__ void sort256x2(float s[8], float t[8], int lane) {
    // phases k=1,2 : fully in-register, compile-time directions
    cmpA(s[0], s[1]); cmpD(s[2], s[3]); cmpA(s[4], s[5]); cmpD(s[6], s[7]);
    cmpA(t[0], t[1]); cmpD(t[2], t[3]); cmpA(t[4], t[5]); cmpD(t[6], t[7]);
    cmpA(s[0], s[2]); cmpA(s[1], s[3]); cmpD(s[4], s[6]); cmpD(s[5], s[7]);
    cmpA(t[0], t[2]); cmpA(t[1], t[3]); cmpD(t[4], t[6]); cmpD(t[5], t[7]);
    cmpA(s[0], s[1]); cmpA(s[2], s[3]); cmpD(s[4], s[5]); cmpD(s[6], s[7]);
    cmpA(t[0], t[1]); cmpA(t[2], t[3]); cmpD(t[4], t[5]); cmpD(t[6], t[7]);
    int b0 = lane & 1, b1 = (lane >> 1) & 1, b2 = (lane >> 2) & 1;
    int b3 = (lane >> 3) & 1, b4 = (lane >> 4) & 1;
    bool k1 = (lane & 1) == 0, k2 = (lane & 2) == 0, k4 = (lane & 4) == 0;
    bool k8 = (lane & 8) == 0, k16 = (lane & 16) == 0;
    // phase 3 (flip = b0)
    negif2(s, t, b0);
    inreg3x2(s, t);
    // phase 4 (flip = b1)
    negif2(s, t, b0 ^ b1);
    shufstage2<1>(s, t, k1);
    inreg3x2(s, t);
    // phase 5 (flip = b2)
    negif2(s, t, b1 ^ b2);
    shufstage2<2>(s, t, k2);
    shufstage2<1>(s, t, k1);
    inreg3x2(s, t);
    // phase 6 (flip = b3)
    negif2(s, t, b2 ^ b3);
    shufstage2<4>(s, t, k4);
    shufstage2<2>(s, t, k2);
    shufstage2<1>(s, t, k1);
    inreg3x2(s, t);
    // phase 7 (flip = b4)
    negif2(s, t, b3 ^ b4);
    shufstage2<8>(s, t, k8);
    shufstage2<4>(s, t, k4);
    shufstage2<2>(s, t, k2);
    shufstage2<1>(s, t, k1);
    inreg3x2(s, t);
    // phase 8 (flip = 0)
    negif2(s, t, b4);
    shufstage2<16>(s, t, k16);
    shufstage2<8>(s, t, k8);
    shufstage2<4>(s, t, k4);
    shufstage2<2>(s, t, k2);
    shufstage2<1>(s, t, k1);
    inreg3x2(s, t);
}

// ---------------------------------------------------------------------------
// Fused: dilated directional diffs -> 16 expansion products -> sort along H
//        -> SiLU -> k4 reduce. Output transposed [b][c][w][h].
// One column per warp; e-channels processed two at a time (dual interleaved
// sorts for ILP). B-side weights derived from k3 via the rotation identity
// (d+4)&7 == d^4, so only one weight table is needed.
template <int S>
__global__ void __launch_bounds__(256) fused_branch(int br) {
    constexpr int NC = 8 + 2 * S;           // columns in tile
    constexpr int CP = 289;
    __shared__ float cs[NC * CP];
    __shared__ float k3s[128];              // [e][d]
    __shared__ float k4s[16];

    int b = blockIdx.z, g = blockIdx.y, w0 = blockIdx.x * 8;
    int tid  = threadIdx.x;
    int lane = tid & 31, warp = tid >> 5;

    if (tid < 128) k3s[tid] = g_k3[(g * 16 + (tid >> 3)) * 8 + (tid & 7)];
    if (tid < 16) k4s[tid] = g_k4[g * 16 + tid];

    const float* cbase = g_c + (size_t)(b * 16 + g) * HW;
    // w-major fill: consecutive threads hit consecutive gmem addresses
    #pragma unroll 1
    for (int j = tid; j < NC * 256; j += 256) {
        int h   = j / NC;
        int col = j - h * NC;
        int wg  = w0 - S + col;
        float v = 0.f;
        if ((unsigned)wg < 256u) v = cbase[h * 256 + wg];
        cs[col * CP + h + (h >> 3)] = v;
    }
    __syncthreads();

    int colc = warp + S;                    // this warp's output column in tile
    const float* pC = cs + colc * CP;
    const float* pL = cs + (colc - S) * CP;
    const float* pR = cs + (colc + S) * CP;

    float cc[8], acc[8];
    #pragma unroll
    for (int r = 0; r < 8; ++r) {
        int h = lane * 8 + r;
        cc[r]  = pC[h + (h >> 3)];
        acc[r] = 0.f;
    }

    #pragma unroll 1
    for (int ep = 0; ep < 8; ++ep) {
        int e0 = 2 * ep, e1 = 2 * ep + 1;
        float wA[8], wB[8];
        #pragma unroll
        for (int d = 0; d < 8; ++d) { wA[d] = k3s[e0 * 8 + d]; wB[d] = k3s[e1 * 8 + d]; }

        float s[8], t[8];
        #pragma unroll
        for (int r = 0; r < 8; ++r) {
            int h  = lane * 8 + r;
            int hm = h - S, hp = h + S;
            bool vm = hm >= 0;
            bool vp = hp < 256;
            int  ai  = h  + (h  >> 3);
            int  aim = hm + (hm >> 3);
            int  aip = hp + (hp >> 3);
            float nbv[8];
            nbv[0] = vm ? pL[aim] : 0.f;
            nbv[1] = vm ? pC[aim] : 0.f;
            nbv[2] = vm ? pR[aim] : 0.f;
            nbv[3] = pL[ai];
            nbv[4] = vp ? pR[aip] : 0.f;
            nbv[5] = vp ? pC[aip] : 0.f;
            nbv[6] = vp ? pL[aip] : 0.f;
            nbv[7] = pR[ai];
            float A0 = 0.f, B0 = 0.f, A1 = 0.f, B1 = 0.f;
            #pragma unroll
            for (int d = 0; d < 8; ++d) {
                A0 = fmaf(nbv[d],     wA[d], A0);
                B0 = fmaf(nbv[d ^ 4], wA[d], B0);
                A1 = fmaf(nbv[d],     wB[d], A1);
                B1 = fmaf(nbv[d ^ 4], wB[d], B1);
            }
            s[r] = (cc[r] - A0) * (cc[r] - B0);
            t[r] = (cc[r] - A1) * (cc[r] - B1);
        }

        sort256x2(s, t, lane);

        float k40 = k4s[e0], k41 = k4s[e1];
        #pragma unroll
        for (int r = 0; r < 8; ++r) {
            float v1 = s[r], v2 = t[r];
            float g1 = 1.f / (1.f + __expf(-v1));
            float g2 = 1.f / (1.f + __expf(-v2));
            acc[r] = fmaf(k40 * v1, g1, acc[r]);
            acc[r] = fmaf(k41 * v2, g2, acc[r]);
        }
    }

    int w = w0 + warp;
    float* op = g_br + (size_t)br * BRS + ((size_t)((b * 16 + g) * 256 + w)) * 256;
    float4 v0 = make_float4(acc[0], acc[1], acc[2], acc[3]);
    float4 v1 = make_float4(acc[4], acc[5], acc[6], acc[7]);
    reinterpret_cast<float4*>(op + lane * 8)[0] = v0;
    reinterpret_cast<float4*>(op + lane * 8)[1] = v1;
}

// ---------------------------------------------------------------------------
__global__ void combine_kernel() {
    int idx = blockIdx.x * 256 + threadIdx.x;   // float4 index
    const float4* p0 = (const float4*)g_br;
    float4 v0 = p0[idx];
    float4 v1 = p0[BRS / 4 + idx];
    float4 v2 = p0[2 * (BRS / 4) + idx];
    float4 v3 = p0[3 * (BRS / 4) + idx];
    float4 o;
    o.x = fmaxf(fmaxf(v0.x, v1.x), fmaxf(v2.x, v3.x)) + 0.25f * (v0.x + v1.x + v2.x + v3.x);
    o.y = fmaxf(fmaxf(v0.y, v1.y), fmaxf(v2.y, v3.y)) + 0.25f * (v0.y + v1.y + v2.y + v3.y);
    o.z = fmaxf(fmaxf(v0.z, v1.z), fmaxf(v2.z, v3.z)) + 0.25f * (v0.z + v1.z + v2.z + v3.z);
    o.w = fmaxf(fmaxf(v0.w, v1.w), fmaxf(v2.w, v3.w)) + 0.25f * (v0.w + v1.w + v2.w + v3.w);
    ((float4*)g_outs)[idx] = o;
}

// ---------------------------------------------------------------------------
// 3x3 conv (no bias) on transposed layout + BN(eval) + SiLU + 1x1 -> sigmoid.
__global__ void post_conv(const float* __restrict__ wb,
                          const float* __restrict__ gamma,
                          const float* __restrict__ beta,
                          const float* __restrict__ mean,
                          const float* __restrict__ var,
                          const float* __restrict__ wout,
                          const float* __restrict__ bout) {
    __shared__ float tile[18][35];
    __shared__ float ws[16 * 9];
    int b  = blockIdx.z;
    int o0 = blockIdx.y * 16, i0 = blockIdx.x * 32;
    int tx = threadIdx.x, ty = threadIdx.y;
    int tid = ty * 32 + tx;
    float acc[16][2];
    #pragma unroll
    for (int co = 0; co < 16; ++co) { acc[co][0] = 0.f; acc[co][1] = 0.f; }
    for (int ci = 0; ci < 16; ++ci) {
        __syncthreads();
        for (int i = tid; i < 144; i += 256) {
            int co = i / 9, rc = i % 9;
            int bi = rc / 3, ao = rc % 3;
            ws[co * 9 + ao * 3 + bi] = wb[(co * 16 + ci) * 9 + bi * 3 + ao];
        }
        const float* xp = g_outs + (size_t)(b * 16 + ci) * HW;
        for (int i = tid; i < 18 * 34; i += 256) {
            int to = i / 34, ti = i - to * 34;
            int oo = o0 + to - 1, ii = i0 + ti - 1;
            tile[to][ti] = ((unsigned)oo < 256u && (unsigned)ii < 256u)
                               ? xp[oo * 256 + ii] : 0.f;
        }
        __syncthreads();
        #pragma unroll
        for (int a = 0; a < 3; ++a)
            #pragma unroll
            for (int bb = 0; bb < 3; ++bb) {
                float v0 = tile[ty + a][tx + bb];
                float v1 = tile[ty + 8 + a][tx + bb];
                #pragma unroll
                for (int co = 0; co < 16; ++co) {
                    float wv = ws[co * 9 + a * 3 + bb];
                    acc[co][0] = fmaf(wv, v0, acc[co][0]);
                    acc[co][1] = fmaf(wv, v1, acc[co][1]);
                }
            }
    }
    float m0 = 0.f, m1 = 0.f;
    #pragma unroll
    for (int co = 0; co < 16; ++co) {
        float sc = __ldg(gamma + co) * rsqrtf(__ldg(var + co) + 1e-5f);
        float sh = __ldg(beta + co) - __ldg(mean + co) * sc;
        float h0 = acc[co][0] * sc + sh;
        float h1 = acc[co][1] * sc + sh;
        h0 = h0 / (1.f + __expf(-h0));
        h1 = h1 / (1.f + __expf(-h1));
        float wv = __ldg(wout + co);
        m0 = fmaf(wv, h0, m0);
        m1 = fmaf(wv, h1, m1);
    }
    float bo = __ldg(bout);
    m0 = 1.f / (1.f + __expf(-(m0 + bo)));
    m1 = 1.f / (1.f + __expf(-(m1 + bo)));
    float* mp = g_mask + (size_t)b * HW + (o0 + ty) * 256 + i0 + tx;
    mp[0]       = m0;
    mp[8 * 256] = m1;
}

// ---------------------------------------------------------------------------
// Final: out = cen * (mask*m*s0 + m*s1 + s2*mask + s3), mask stored [b][w][h].
__global__ void final_kernel(const float* __restrict__ cen,
                             const float* __restrict__ mas,
                             float* __restrict__ out) {
    __shared__ float mt[32][33];
    int b  = blockIdx.z;
    int h0 = blockIdx.x * 32, w0 = blockIdx.y * 32;
    int tx = threadIdx.x, ty = threadIdx.y;
    #pragma unroll
    for (int k = 0; k < 4; ++k) {
        int wi = ty * 4 + k;
        mt[wi][tx] = g_mask[(size_t)b * HW + (w0 + wi) * 256 + h0 + tx];
    }
    __syncthreads();
    float s0 = g_s1[0], s1 = g_s1[1], s2 = g_s1[2], s3 = g_s1[3];
    int w = w0 + tx;
    #pragma unroll
    for (int k = 0; k < 4; ++k) {
        int h = h0 + ty * 4 + k;
        float mv = mt[tx][ty * 4 + k];
        float ms = mas[(size_t)b * HW + h * 256 + w];
        float m  = 1.f / (1.f + __expf(-ms));
        float coef = m * fmaf(mv, s0, s1) + fmaf(s2, mv, s3);
        size_t base = (size_t)b * 64 * HW + (size_t)h * 256 + w;
        #pragma unroll 4
        for (int c = 0; c < 64; ++c) {
            size_t o = base + (size_t)c * HW;
            out[o] = cen[o] * coef;
        }
    }
}

// ---------------------------------------------------------------------------
extern "C" void kernel_launch(void* const* d_in, const int* in_sizes, int n_in,
                              void* d_out, int out_size) {
    const float* cen      = (const float*)d_in[0];
    const float* mas      = (const float*)d_in[1];
    const float* w_in     = (const float*)d_in[2];
    const float* b_in     = (const float*)d_in[3];
    const float* w_c0     = (const float*)d_in[4];
    const float* b_c0     = (const float*)d_in[5];
    const float* w_c1     = (const float*)d_in[6];
    const float* b_c1     = (const float*)d_in[7];
    const float* w_c2     = (const float*)d_in[8];
    const float* b_c2     = (const float*)d_in[9];
    const float* w_c3     = (const float*)d_in[10];
    const float* b_c3     = (const float*)d_in[11];
    const float* scales1  = (const float*)d_in[12];
    const float* scales2  = (const float*)d_in[13];
    const float* scales3  = (const float*)d_in[14];
    const float* w_base   = (const float*)d_in[15];
    const float* bn_gamma = (const float*)d_in[16];
    const float* bn_beta  = (const float*)d_in[17];
    const float* bn_mean  = (const float*)d_in[18];
    const float* bn_var   = (const float*)d_in[19];
    const float* w_out    = (const float*)d_in[20];
    const float* b_out    = (const float*)d_in[21];
    float* out = (float*)d_out;

    prep_kernel<<<1, 256>>>(scales1, scales2, scales3);
    in_conv<<<1024, 256>>>(cen, w_in, b_in);

    dim3 cgrid(8, 16, 4), cblk(32, 8);
    dim3 fgrid(32, 16, 4);

    mid_conv<1><<<cgrid, cblk>>>(w_c0, b_c0);
    fused_branch<1><<<fgrid, 256>>>(0);

    mid_conv<3><<<cgrid, cblk>>>(w_c1, b_c1);
    fused_branch<3><<<fgrid, 256>>>(1);

    mid_conv<5><<<cgrid, cblk>>>(w_c2, b_c2);
    fused_branch<5><<<fgrid, 256>>>(2);

    mid_conv<7><<<cgrid, cblk>>>(w_c3, b_c3);
    fused_branch<7><<<fgrid, 256>>>(3);

    combine_kernel<<<BRS / 1024, 256>>>();

    post_conv<<<cgrid, cblk>>>(w_base, bn_gamma, bn_beta, bn_mean, bn_var,
                               w_out, b_out);

    final_kernel<<<dim3(8, 8, 4), dim3(32, 8)>>>(cen, mas, out);
}